// round 4
// baseline (speedup 1.0000x reference)
#include <cuda_runtime.h>
#include <cuda_bf16.h>
#include <cstdint>

// ---------------- problem constants ----------------
#define SEQ   8192
#define EMB   768
#define HD    512          // per-direction hidden
#define G4    2048         // 4*HD
#define NTAG  14
#define START_IDX 12
#define STOP_IDX  13
#define NEGBIG (-1e30f)

#define REC_BLOCKS_PER_DIR 32   // 32+32 = 64 CTAs of 512 threads, all co-resident
#define CHUNK  64               // CRF chunk length
#define NCHUNK (SEQ / CHUNK)    // 128

// ---------------- device scratch (static; no allocations) ----------------
__device__ float    g_xg[2][SEQ * G4];          // gate-interleaved: [t][dim][gate]
__device__ float    g_hs[2][SEQ * HD];          // per-direction hidden states
__device__ float    g_feats[SEQ * NTAG];
__device__ float    g_hbuf[2][2][HD];           // [dir][buf][dim]
__device__ unsigned g_bar[2][32];               // per-direction barrier counter (padded)
__device__ float    g_chunkM[NCHUNK][NTAG][NTAG];

// ---------------- helpers ----------------
__device__ __forceinline__ float sigf(float x) {
    return __fdividef(1.0f, 1.0f + __expf(-x));
}
__device__ __forceinline__ float tanh_fast(float x) {
    float a = fabsf(x);
    float e = __expf(-2.0f * a);                 // in (0,1], never overflows
    float t = __fdividef(1.0f - e, 1.0f + e);
    return copysignf(t, x);
}

// =====================================================================
// 1) GEMM: xg[dir] = embeds @ w_ih^T  (+ b_ih + b_hh), gate-interleaved
//    inner product via packed fma.rn.f32x2 (FFMA2) -> 2 MACs per FMA op
// =====================================================================
#define BM 128
#define BN 128
#define BK 16
__global__ void __launch_bounds__(256, 2) gemm_xg(
    const float* __restrict__ emb,
    const float* __restrict__ wih_f, const float* __restrict__ bih_f, const float* __restrict__ bhh_f,
    const float* __restrict__ wih_b, const float* __restrict__ bih_b, const float* __restrict__ bhh_b)
{
    const int dir = blockIdx.z;
    const float* __restrict__ W  = dir ? wih_b : wih_f;
    const float* __restrict__ b1 = dir ? bih_b : bih_f;
    const float* __restrict__ b2 = dir ? bhh_b : bhh_f;
    float* __restrict__ out = g_xg[dir];

    __shared__ float As[BK][BM + 4];
    __shared__ float Bs[BK][BN + 4];

    const int tx = threadIdx.x;                  // 0..255
    const int m0 = blockIdx.y * BM;
    const int n0 = blockIdx.x * BN;
    const int tm = (tx >> 4) * 8;                // 0..120
    const int tn = (tx & 15) * 8;                // 0..120 (even)

    uint64_t accp[8][4];                         // packed f32x2 accumulators
    #pragma unroll
    for (int i = 0; i < 8; i++)
        #pragma unroll
        for (int jp = 0; jp < 4; jp++) accp[i][jp] = 0ull;  // (0.f,0.f)

    for (int k0 = 0; k0 < EMB; k0 += BK) {
        // load A tile (128 x 16) transposed into As[k][m]
        #pragma unroll
        for (int i = 0; i < 2; i++) {
            int idx = tx + i * 256;              // 0..511 float4 slots
            int r   = idx >> 2;
            int c4  = (idx & 3) * 4;
            float4 v = *(const float4*)&emb[(m0 + r) * EMB + k0 + c4];
            As[c4 + 0][r] = v.x; As[c4 + 1][r] = v.y;
            As[c4 + 2][r] = v.z; As[c4 + 3][r] = v.w;
        }
        // load B tile: w_ih rows n0..n0+127, cols k0..k0+15 -> Bs[k][n]
        #pragma unroll
        for (int i = 0; i < 2; i++) {
            int idx = tx + i * 256;
            int r   = idx >> 2;
            int c4  = (idx & 3) * 4;
            float4 v = *(const float4*)&W[(n0 + r) * EMB + k0 + c4];
            Bs[c4 + 0][r] = v.x; Bs[c4 + 1][r] = v.y;
            Bs[c4 + 2][r] = v.z; Bs[c4 + 3][r] = v.w;
        }
        __syncthreads();
        #pragma unroll
        for (int kk = 0; kk < BK; kk++) {
            uint64_t bp[4];
            #pragma unroll
            for (int jp = 0; jp < 4; jp++)
                bp[jp] = *(const uint64_t*)&Bs[kk][tn + jp * 2];  // 8B-aligned pairs
            #pragma unroll
            for (int i = 0; i < 8; i++) {
                float av = As[kk][tm + i];
                uint64_t ad;
                asm("mov.b64 %0, {%1, %1};" : "=l"(ad) : "f"(av));
                #pragma unroll
                for (int jp = 0; jp < 4; jp++)
                    asm("fma.rn.f32x2 %0, %1, %2, %3;"
                        : "=l"(accp[i][jp])
                        : "l"(ad), "l"(bp[jp]), "l"(accp[i][jp]));
            }
        }
        __syncthreads();
    }

    // store with gate-interleave remap: logical row r -> [t*2048 + (r&511)*4 + (r>>9)]
    #pragma unroll
    for (int i = 0; i < 8; i++) {
        int t = m0 + tm + i;
        #pragma unroll
        for (int jp = 0; jp < 4; jp++) {
            float lo, hi;
            asm("mov.b64 {%0, %1}, %2;" : "=f"(lo), "=f"(hi) : "l"(accp[i][jp]));
            int r0 = n0 + tn + jp * 2;
            int r1 = r0 + 1;
            out[t * G4 + ((r0 & (HD - 1)) << 2) + (r0 >> 9)] = lo + b1[r0] + b2[r0];
            out[t * G4 + ((r1 & (HD - 1)) << 2) + (r1 >> 9)] = hi + b1[r1] + b2[r1];
        }
    }
}

// =====================================================================
// 2) init: h0 into buffers, reset barriers (runs every launch/replay)
// =====================================================================
__global__ void init_state(const float* __restrict__ h0)
{
    int i = threadIdx.x;                         // 512 threads
    g_hbuf[0][0][i] = h0[i];
    g_hbuf[1][0][i] = h0[HD + i];
    if (i < 2) g_bar[i][0] = 0u;
}

// =====================================================================
// 3) BiLSTM recurrence: persistent, 64 CTAs x 512 thr, release/acquire barrier
// =====================================================================
__global__ void __launch_bounds__(512, 1) lstm_rec(
    const float* __restrict__ whh_f,
    const float* __restrict__ whh_b,
    const float* __restrict__ c0)
{
    const int dir = blockIdx.x >> 5;             // 32 blocks per direction
    const int blk = blockIdx.x & 31;
    const int w   = threadIdx.x >> 5;            // warp 0..15
    const int l   = threadIdx.x & 31;
    const int j   = blk * 16 + w;                // owned h-dim

    const float* __restrict__ W  = dir ? whh_b : whh_f;
    const float* __restrict__ xg = g_xg[dir];
    float* __restrict__ hs = g_hs[dir];
    float* hb0 = g_hbuf[dir][0];
    float* hb1 = g_hbuf[dir][1];
    unsigned* bar = &g_bar[dir][0];

    // weights register-resident; lane l covers k = l, l+32, ..., l+480
    float wr[4][16];
    #pragma unroll
    for (int g = 0; g < 4; g++) {
        const float* wrow = &W[(g * HD + j) * HD];
        #pragma unroll
        for (int kk = 0; kk < 16; kk++) wr[g][kk] = wrow[kk * 32 + l];
    }
    float c = c0[dir * HD + j];

    __shared__ float hsh[HD];

    // stage initial h (1 float / thread)
    hsh[threadIdx.x] = __ldcg(&hb0[threadIdx.x]);
    __syncthreads();

    // prefetch xg for step 0 (broadcast load, warp-uniform address)
    int s0 = dir ? (SEQ - 1) : 0;
    float4 xv = *(const float4*)&xg[s0 * G4 + j * 4];

    for (int t = 0; t < SEQ; t++) {
        const int s = dir ? (SEQ - 1 - t) : t;

        // prefetch next step's xg early (hides DRAM latency by a full step)
        float4 xv_next;
        if (t + 1 < SEQ) {
            int sn = dir ? (SEQ - 2 - t) : (t + 1);
            xv_next = *(const float4*)&xg[sn * G4 + j * 4];
        } else {
            xv_next = make_float4(0.f, 0.f, 0.f, 0.f);
        }

        // h chunk from smem
        float h[16];
        #pragma unroll
        for (int kk = 0; kk < 16; kk++) h[kk] = hsh[kk * 32 + l];

        float d0 = 0.f, d1 = 0.f, d2 = 0.f, d3 = 0.f;
        #pragma unroll
        for (int kk = 0; kk < 16; kk++) {
            d0 = fmaf(wr[0][kk], h[kk], d0);
            d1 = fmaf(wr[1][kk], h[kk], d1);
            d2 = fmaf(wr[2][kk], h[kk], d2);
            d3 = fmaf(wr[3][kk], h[kk], d3);
        }
        #pragma unroll
        for (int off = 16; off > 0; off >>= 1) {
            d0 += __shfl_down_sync(0xffffffffu, d0, off);
            d1 += __shfl_down_sync(0xffffffffu, d1, off);
            d2 += __shfl_down_sync(0xffffffffu, d2, off);
            d3 += __shfl_down_sync(0xffffffffu, d3, off);
        }

        float* hdst = (t & 1) ? hb0 : hb1;
        if (l == 0) {
            float gi = xv.x + d0;
            float gf = xv.y + d1;
            float gg = xv.z + d2;
            float go = xv.w + d3;
            c = sigf(gf) * c + sigf(gi) * tanh_fast(gg);
            float hn = sigf(go) * tanh_fast(c);
            __stcg(&hdst[j], hn);                // L2-visible for other SMs
            hs[s * HD + j] = hn;
        }
        xv = xv_next;

        __syncthreads();                          // block's h stores issued & block-ordered
        if (threadIdx.x == 0) {
            // release-arrive: publishes this block's (and, transitively via
            // __syncthreads, all its threads') prior stores at GPU scope
            asm volatile("red.release.gpu.global.add.u32 [%0], %1;"
                         :: "l"(bar), "r"(1u) : "memory");
            const unsigned target = (unsigned)REC_BLOCKS_PER_DIR * (unsigned)(t + 1);
            unsigned v;
            do {
                asm volatile("ld.acquire.gpu.global.u32 %0, [%1];"
                             : "=r"(v) : "l"(bar) : "memory");
            } while (v < target);
        }
        __syncthreads();

        // stage the just-produced h for the next step (1 float / thread)
        if (t + 1 < SEQ) {
            const float* hsrc = (t & 1) ? hb0 : hb1;
            hsh[threadIdx.x] = __ldcg(&hsrc[threadIdx.x]);
            __syncthreads();
        }
    }
}

// =====================================================================
// 4) feats[t, j] = [hs_f | hs_b] . w_tag[j] + b_tag[j]  (h staged once/block)
// =====================================================================
__global__ void feats_kernel(const float* __restrict__ w_tag,
                             const float* __restrict__ b_tag)
{
    __shared__ float hsm[2 * HD];
    const int t = blockIdx.x;
    for (int i = threadIdx.x; i < 2 * HD; i += NTAG * 32)
        hsm[i] = (i < HD) ? g_hs[0][t * HD + i] : g_hs[1][t * HD + (i - HD)];
    __syncthreads();

    const int w = threadIdx.x >> 5;              // 0..13 (tag)
    const int l = threadIdx.x & 31;
    const float* __restrict__ wt = &w_tag[w * (2 * HD)];

    float acc = 0.f;
    #pragma unroll
    for (int k = l; k < 2 * HD; k += 32)
        acc = fmaf(hsm[k], __ldg(&wt[k]), acc);
    #pragma unroll
    for (int off = 16; off > 0; off >>= 1)
        acc += __shfl_down_sync(0xffffffffu, acc, off);
    if (l == 0) g_feats[t * NTAG + w] = acc + b_tag[w];
}

// =====================================================================
// 5) CRF chunk matrices (log-semiring): Ms <- M_t (o) Ms, 64 steps/chunk
// =====================================================================
__global__ void crf_chunk(const float* __restrict__ trans)
{
    __shared__ float Ms[NTAG][NTAG + 2];
    const int tid = threadIdx.x;                 // 0..195
    const int j = tid / NTAG;
    const int i = tid % NTAG;

    float trow[NTAG];
    #pragma unroll
    for (int k = 0; k < NTAG; k++) trow[k] = trans[j * NTAG + k];

    Ms[j][i] = (i == j) ? 0.f : NEGBIG;          // semiring identity
    __syncthreads();

    const int base = blockIdx.x * CHUNK;
    for (int t = base; t < base + CHUNK; t++) {
        float fj = g_feats[t * NTAG + j];
        float vals[NTAG];
        float m = NEGBIG;
        #pragma unroll
        for (int k = 0; k < NTAG; k++) {
            vals[k] = trow[k] + Ms[k][i];
            m = fmaxf(m, vals[k]);
        }
        float s = 0.f;
        #pragma unroll
        for (int k = 0; k < NTAG; k++) s += __expf(vals[k] - m);
        float nv = m + __logf(s) + fj;
        __syncthreads();
        Ms[j][i] = nv;
        __syncthreads();
    }
    g_chunkM[blockIdx.x][j][i] = Ms[j][i];
}

// =====================================================================
// 6) gold score (parallel reduce) + chunk composition + final output
// =====================================================================
__global__ void crf_final(const float* __restrict__ trans,
                          const int* __restrict__ tags,
                          float* __restrict__ out)
{
    __shared__ float red[256];
    const int tid = threadIdx.x;

    // gold: emit + transition scores
    float part = 0.f;
    for (int t = tid; t < SEQ; t += 256) {
        int tag  = tags[t];
        int prev = (t == 0) ? START_IDX : tags[t - 1];
        part += g_feats[t * NTAG + tag] + trans[tag * NTAG + prev];
    }
    red[tid] = part;
    __syncthreads();
    #pragma unroll
    for (int s = 128; s > 0; s >>= 1) {
        if (tid < s) red[tid] += red[tid + s];
        __syncthreads();
    }
    const float gold = red[0] + trans[STOP_IDX * NTAG + tags[SEQ - 1]];

    // compose 128 chunk matrices into the init vector (warp 0)
    if (tid < 32) {
        const int l = tid;
        float fv = (l < NTAG) ? ((l == START_IDX) ? 0.f : NEGBIG) : NEGBIG;
        for (int cix = 0; cix < NCHUNK; cix++) {
            float vals[NTAG];
            float m = NEGBIG;
            #pragma unroll
            for (int i = 0; i < NTAG; i++) {
                float fvi = __shfl_sync(0xffffffffu, fv, i);
                float v = (l < NTAG) ? (g_chunkM[cix][l][i] + fvi) : NEGBIG;
                vals[i] = v;
                m = fmaxf(m, v);
            }
            float s = 0.f;
            #pragma unroll
            for (int i = 0; i < NTAG; i++) s += __expf(vals[i] - m);
            float nv = m + __logf(s);
            fv = (l < NTAG) ? nv : NEGBIG;
        }
        // forward = LSE_l(fv[l] + trans[STOP, l])
        float v = (l < NTAG) ? (fv + trans[STOP_IDX * NTAG + l]) : NEGBIG;
        float m = v;
        #pragma unroll
        for (int off = 16; off > 0; off >>= 1)
            m = fmaxf(m, __shfl_xor_sync(0xffffffffu, m, off));
        float e = __expf(v - m);
        #pragma unroll
        for (int off = 16; off > 0; off >>= 1)
            e += __shfl_xor_sync(0xffffffffu, e, off);
        float fwd = m + __logf(e);
        if (l == 0) out[0] = fwd - gold;
    }
}

// =====================================================================
// launch
// =====================================================================
extern "C" void kernel_launch(void* const* d_in, const int* in_sizes, int n_in,
                              void* d_out, int out_size)
{
    const float* embeds = (const float*)d_in[0];
    const int*   tags   = (const int*)  d_in[1];
    const float* w_ih_f = (const float*)d_in[2];
    const float* w_hh_f = (const float*)d_in[3];
    const float* b_ih_f = (const float*)d_in[4];
    const float* b_hh_f = (const float*)d_in[5];
    const float* w_ih_b = (const float*)d_in[6];
    const float* w_hh_b = (const float*)d_in[7];
    const float* b_ih_b = (const float*)d_in[8];
    const float* b_hh_b = (const float*)d_in[9];
    const float* w_tag  = (const float*)d_in[10];
    const float* b_tag  = (const float*)d_in[11];
    const float* trans  = (const float*)d_in[12];
    const float* h0     = (const float*)d_in[13];
    const float* c0     = (const float*)d_in[14];
    float* out = (float*)d_out;

    dim3 gemm_grid(G4 / BN, SEQ / BM, 2);        // (16, 64, 2)
    gemm_xg<<<gemm_grid, 256>>>(embeds,
                                w_ih_f, b_ih_f, b_hh_f,
                                w_ih_b, b_ih_b, b_hh_b);

    init_state<<<1, 512>>>(h0);

    lstm_rec<<<2 * REC_BLOCKS_PER_DIR, 512>>>(w_hh_f, w_hh_b, c0);

    feats_kernel<<<SEQ, NTAG * 32>>>(w_tag, b_tag);

    crf_chunk<<<NCHUNK, NTAG * NTAG>>>(trans);

    crf_final<<<1, 256>>>(trans, tags, out);
}